// round 15
// baseline (speedup 1.0000x reference)
#include <cuda_runtime.h>
#include <cuda_fp16.h>
#include <mma.h>
#include <stdint.h>
using namespace nvcuda;

#define N_NODES 100000
#define F_IN    128
#define HDIM    64
#define CDIM    40

// ---- scratch (device globals: no allocation allowed) ----
__device__ __align__(256) int    g_cnt [N_NODES];
__device__ __align__(256) float  g_dinv[N_NODES];
__device__ __align__(256) __half g_W1h [128 * 72];        // W1 f16, padded stride 72
__device__ __align__(256) __half g_W2h [64 * 56];         // W2 f16, padded stride 56
__device__ __align__(256) __half g_h1s [N_NODES * HDIM];  // (x@W1)*dinv[row], f16
__device__ __align__(256) __half g_agg1[N_NODES * HDIM];  // init=self, += h1s[src]
__device__ __align__(256) __half g_h2s [N_NODES * CDIM];
__device__ __align__(256) __half g_agg2[N_NODES * CDIM];

// ---- weight conversion helper (runs in blocks 0/1 of the count kernels) ----
__device__ __forceinline__ void conv_weights(int bid, int tid,
                                             const float* __restrict__ W1,
                                             const float* __restrict__ W2) {
    if (bid == 0) {               // W1 -> f16 padded [128][72]
        for (int i = tid; i < 128 * 72; i += 256) {
            int k = i / 72, n = i % 72;
            g_W1h[i] = __float2half_rn(n < 64 ? W1[k * 64 + n] : 0.f);
        }
    } else if (bid == 1) {        // W2 -> f16 padded [64][56]
        for (int i = tid; i < 64 * 56; i += 256) {
            int k = i / 56, n = i % 56;
            g_W2h[i] = __float2half_rn(n < 40 ? W2[k * 40 + n] : 0.f);
        }
    }
}

// ------------------ degree count (vectorized): 4 edges/thread ---------------
__global__ void k_count_vec(const int4* __restrict__ dst4, int n4, int rem,
                            const float* __restrict__ W1,
                            const float* __restrict__ W2) {
    conv_weights(blockIdx.x, threadIdx.x, W1, W2);
    int i = blockIdx.x * blockDim.x + threadIdx.x;
    if (i < n4) {
        int4 d = __ldcg(&dst4[i]);
        if ((unsigned)d.x < (unsigned)N_NODES) atomicAdd(&g_cnt[d.x], 1);
        if ((unsigned)d.y < (unsigned)N_NODES) atomicAdd(&g_cnt[d.y], 1);
        if ((unsigned)d.z < (unsigned)N_NODES) atomicAdd(&g_cnt[d.z], 1);
        if ((unsigned)d.w < (unsigned)N_NODES) atomicAdd(&g_cnt[d.w], 1);
    }
    if (blockIdx.x == 2 && threadIdx.x == 0) {   // tail (< 4 edges)
        const int* t = (const int*)(dst4 + n4);
        for (int q = 0; q < rem; q++) {
            int d = __ldcg(&t[q]);
            if ((unsigned)d < (unsigned)N_NODES) atomicAdd(&g_cnt[d], 1);
        }
    }
}

// scalar fallback (misaligned dst column)
__global__ void k_count(const int* __restrict__ ei, int E,
                        const float* __restrict__ W1,
                        const float* __restrict__ W2) {
    conv_weights(blockIdx.x, threadIdx.x, W1, W2);
    int e = blockIdx.x * blockDim.x + threadIdx.x;
    if (e >= E) return;
    int d = __ldcg(&ei[E + e]);
    if ((unsigned)d < (unsigned)N_NODES) atomicAdd(&g_cnt[d], 1);
}

// ---- GEMM1 (tensor cores, pipelined, pre-converted W1h) ----------------------
#define WN 72
#define XS 40
#define ES 72
#define G1_SMEM (128*WN*2 + 2*128*XS*2)
__global__ __launch_bounds__(256, 3) void k_gemm1(const float* __restrict__ x) {
    __shared__ __align__(32) unsigned char sraw[G1_SMEM];
    __half* Wh  = (__half*)sraw;
    __half* Xh0 = (__half*)(sraw + 128 * WN * 2);
    __half* Xh1 = (__half*)(sraw + 128 * WN * 2 + 128 * XS * 2);
    float*  Es  = (float*)sraw;

    const int tid = threadIdx.x;
    const int wid = tid >> 5;
    const int warp_m = wid >> 1;
    const int warp_n = wid & 1;
    const int rowBase = blockIdx.x * 128;

    const int srow  = tid >> 1;
    const int kkOff = (tid & 1) * 16;
    const int grow  = rowBase + srow;
    const bool rowOK = (grow < N_NODES);
    const float* xrow = &x[(long long)grow * F_IN + kkOff];

    {   // copy pre-converted W1h (18432B) into smem
        const uint4* src = (const uint4*)g_W1h;
        uint4* dst = (uint4*)Wh;
        #pragma unroll
        for (int i = tid; i < 128 * WN * 2 / 16; i += 256) dst[i] = src[i];
    }

    {   // stage chunk 0
        __half* s = &Xh0[srow * XS + kkOff];
        if (rowOK) {
            #pragma unroll
            for (int q = 0; q < 4; q++) {
                float4 v = *(const float4*)(xrow + q * 4);
                *(__half2*)(s + q * 4)     = __float22half2_rn(make_float2(v.x, v.y));
                *(__half2*)(s + q * 4 + 2) = __float22half2_rn(make_float2(v.z, v.w));
            }
        } else {
            #pragma unroll
            for (int q = 0; q < 8; q++) *(__half2*)(s + q * 2) = __float2half2_rn(0.f);
        }
    }

    wmma::fragment<wmma::accumulator, 16, 16, 16, float> c[2][2];
    #pragma unroll
    for (int i = 0; i < 2; i++)
        #pragma unroll
        for (int j = 0; j < 2; j++) wmma::fill_fragment(c[i][j], 0.f);

    __syncthreads();

    #pragma unroll
    for (int ch = 0; ch < 4; ch++) {
        float4 p0, p1, p2, p3;
        if (ch < 3 && rowOK) {
            const float* xp = xrow + (ch + 1) * 32;
            p0 = *(const float4*)(xp);
            p1 = *(const float4*)(xp + 4);
            p2 = *(const float4*)(xp + 8);
            p3 = *(const float4*)(xp + 12);
        }

        const __half* Xb = (ch & 1) ? Xh1 : Xh0;
        #pragma unroll
        for (int kk = 0; kk < 32; kk += 16) {
            wmma::fragment<wmma::matrix_a, 16, 16, 16, __half, wmma::row_major> a[2];
            wmma::fragment<wmma::matrix_b, 16, 16, 16, __half, wmma::row_major> b[2];
            #pragma unroll
            for (int i = 0; i < 2; i++)
                wmma::load_matrix_sync(a[i], &Xb[(warp_m * 32 + i * 16) * XS + kk], XS);
            #pragma unroll
            for (int j = 0; j < 2; j++)
                wmma::load_matrix_sync(b[j], &Wh[(ch * 32 + kk) * WN + warp_n * 32 + j * 16], WN);
            #pragma unroll
            for (int i = 0; i < 2; i++)
                #pragma unroll
                for (int j = 0; j < 2; j++)
                    wmma::mma_sync(c[i][j], a[i], b[j], c[i][j]);
        }

        if (ch < 3) {
            __half* s = ((ch & 1) ? Xh0 : Xh1) + srow * XS + kkOff;
            if (rowOK) {
                *(__half2*)(s)      = __float22half2_rn(make_float2(p0.x, p0.y));
                *(__half2*)(s + 2)  = __float22half2_rn(make_float2(p0.z, p0.w));
                *(__half2*)(s + 4)  = __float22half2_rn(make_float2(p1.x, p1.y));
                *(__half2*)(s + 6)  = __float22half2_rn(make_float2(p1.z, p1.w));
                *(__half2*)(s + 8)  = __float22half2_rn(make_float2(p2.x, p2.y));
                *(__half2*)(s + 10) = __float22half2_rn(make_float2(p2.z, p2.w));
                *(__half2*)(s + 12) = __float22half2_rn(make_float2(p3.x, p3.y));
                *(__half2*)(s + 14) = __float22half2_rn(make_float2(p3.z, p3.w));
            } else {
                #pragma unroll
                for (int q = 0; q < 8; q++) *(__half2*)(s + q * 2) = __float2half2_rn(0.f);
            }
        }
        __syncthreads();
    }

    #pragma unroll
    for (int i = 0; i < 2; i++)
        #pragma unroll
        for (int j = 0; j < 2; j++)
            wmma::store_matrix_sync(&Es[(warp_m * 32 + i * 16) * ES + warp_n * 32 + j * 16],
                                    c[i][j], ES, wmma::mem_row_major);
    __syncthreads();

    {   // epilogue: dinv inline, scale, pack f16, dual-store
        int cb = (tid & 1) * 32;
        if (rowOK) {
            float s = rsqrtf(1.0f + (float)g_cnt[grow]);
            if (cb == 0) g_dinv[grow] = s;
            const float* ep = &Es[srow * ES + cb];
            __half* d1 = &g_h1s [(long long)grow * HDIM + cb];
            __half* d2 = &g_agg1[(long long)grow * HDIM + cb];
            #pragma unroll
            for (int q = 0; q < 8; q++) {
                float4 v = *(const float4*)(ep + q * 4);
                __half2 h0 = __float22half2_rn(make_float2(v.x * s, v.y * s));
                __half2 h1 = __float22half2_rn(make_float2(v.z * s, v.w * s));
                uint2 pk = make_uint2(*(unsigned*)&h0, *(unsigned*)&h1);
                *(uint2*)(d1 + q * 4) = pk;
                *(uint2*)(d2 + q * 4) = pk;
            }
        }
    }
}

// -------- scatter1: agg1[dst] += h1s[src], 2 independent chains per thread ------
__device__ __forceinline__ void sc1_one(const int* __restrict__ ei, int E, long long idx) {
    int e = (int)(idx >> 3);
    int c = ((int)idx & 7) * 8;
    int s = __ldcg(&ei[e]), d = __ldcg(&ei[E + e]);
    if ((unsigned)s >= (unsigned)N_NODES || (unsigned)d >= (unsigned)N_NODES) return;
    uint4 v = __ldcg((const uint4*)&g_h1s[(long long)s * HDIM + c]);
    __half* p = &g_agg1[(long long)d * HDIM + c];
    asm volatile("red.global.add.noftz.v4.f16x2 [%0], {%1, %2, %3, %4};"
                 :: "l"(p), "r"(v.x), "r"(v.y), "r"(v.z), "r"(v.w) : "memory");
}

__global__ void k_scatter1(const int* __restrict__ ei, int E) {
    long long half = ((long long)E * 8) >> 1;
    long long idx = (long long)blockIdx.x * blockDim.x + threadIdx.x;
    if (idx >= half) return;
    sc1_one(ei, E, idx);
    sc1_one(ei, E, idx + half);
}

// ---- GEMM2 (tensor cores, 64-row tiles, per-warp Es epilogue) ----------------
#define W2S 56
#define X2S 72
#define E2S 48    // per-warp Es row stride (floats)
#define G2_SMEM (64*W2S*2 + 64*X2S*2 + 4*16*E2S*4)   // 28672
__global__ __launch_bounds__(256, 6) void k_gemm2(const float* __restrict__ b1) {
    __shared__ __align__(32) unsigned char sraw[G2_SMEM];
    __half* Wh = (__half*)sraw;
    __half* Xh = (__half*)(sraw + 64 * W2S * 2);
    float*  Es = (float*)(sraw + 64 * W2S * 2 + 64 * X2S * 2);  // [4 warps][16][48]
    __shared__ float Bs[64];

    const int tid = threadIdx.x;
    const int wid = tid >> 5;
    const int lane = tid & 31;
    const int rowBase = blockIdx.x * 64;

    const int srow = tid >> 2;
    const int kb   = (tid & 3) * 16;
    const int grow = rowBase + srow;
    const bool rowOK = (grow < N_NODES);

    __half2 xa[8];
    float di = 0.f;
    if (rowOK) {
        di = g_dinv[grow];
        const __half2* ap = (const __half2*)&g_agg1[(long long)grow * HDIM + kb];
        #pragma unroll
        for (int q = 0; q < 8; q++) xa[q] = __ldcg(&ap[q]);
    }

    {   // copy pre-converted W2h (7168B) into smem
        const uint4* src = (const uint4*)g_W2h;
        uint4* dst = (uint4*)Wh;
        #pragma unroll
        for (int i = tid; i < 64 * W2S * 2 / 16; i += 256) dst[i] = src[i];
    }
    if (tid < 64) Bs[tid] = b1[tid];
    __syncthreads();

    {   // convert: relu(dinv*agg1 + b1) -> f16 smem
        __half* s = &Xh[srow * X2S + kb];
        if (rowOK) {
            #pragma unroll
            for (int q = 0; q < 8; q++) {
                float2 f = __half22float2(xa[q]);
                float2 v = make_float2(fmaxf(di * f.x + Bs[kb + q*2],     0.f),
                                       fmaxf(di * f.y + Bs[kb + q*2 + 1], 0.f));
                *(__half2*)(s + q * 2) = __float22half2_rn(v);
            }
        } else {
            #pragma unroll
            for (int q = 0; q < 8; q++) *(__half2*)(s + q * 2) = __float2half2_rn(0.f);
        }
    }
    __syncthreads();   // last block-wide sync: Xh ready

    if (wid < 4) {     // mma warps run to completion independently
        wmma::fragment<wmma::accumulator, 16, 16, 16, float> c[3];
        #pragma unroll
        for (int j = 0; j < 3; j++) wmma::fill_fragment(c[j], 0.f);

        #pragma unroll
        for (int k = 0; k < 64; k += 16) {
            wmma::fragment<wmma::matrix_a, 16, 16, 16, __half, wmma::row_major> a;
            wmma::load_matrix_sync(a, &Xh[(wid * 16) * X2S + k], X2S);
            #pragma unroll
            for (int j = 0; j < 3; j++) {
                wmma::fragment<wmma::matrix_b, 16, 16, 16, __half, wmma::row_major> b;
                wmma::load_matrix_sync(b, &Wh[k * W2S + j * 16], W2S);
                wmma::mma_sync(c[j], a, b, c[j]);
            }
        }

        float* EsW = Es + wid * 16 * E2S;
        #pragma unroll
        for (int j = 0; j < 3; j++)
            wmma::store_matrix_sync(&EsW[j * 16], c[j], E2S, wmma::mem_row_major);
        __syncwarp();

        {   // per-warp epilogue: 16 rows x 2 halves
            int r  = lane >> 1;
            int cb = (lane & 1) * 20;
            int row = rowBase + wid * 16 + r;
            if (row < N_NODES) {
                float s = g_dinv[row];
                const float* ep = &EsW[r * E2S + cb];
                __half* d1 = &g_h2s [(long long)row * CDIM + cb];
                __half* d2 = &g_agg2[(long long)row * CDIM + cb];
                #pragma unroll
                for (int q = 0; q < 5; q++) {
                    float4 v = *(const float4*)(ep + q * 4);
                    __half2 h0 = __float22half2_rn(make_float2(v.x * s, v.y * s));
                    __half2 h1 = __float22half2_rn(make_float2(v.z * s, v.w * s));
                    uint2 pk = make_uint2(*(unsigned*)&h0, *(unsigned*)&h1);
                    *(uint2*)(d1 + q * 4) = pk;
                    *(uint2*)(d2 + q * 4) = pk;
                }
            }
        }
    }
}

// -------- scatter2: agg2[dst] += h2s[src], 2 independent chains per thread ------
__device__ __forceinline__ void sc2_one(const int* __restrict__ ei, int E, long long idx) {
    int e = (int)(idx / 5);
    int c = (int)(idx % 5) * 8;
    int s = __ldcg(&ei[e]), d = __ldcg(&ei[E + e]);
    if ((unsigned)s >= (unsigned)N_NODES || (unsigned)d >= (unsigned)N_NODES) return;
    uint4 v = __ldcg((const uint4*)&g_h2s[(long long)s * CDIM + c]);
    __half* p = &g_agg2[(long long)d * CDIM + c];
    asm volatile("red.global.add.noftz.v4.f16x2 [%0], {%1, %2, %3, %4};"
                 :: "l"(p), "r"(v.x), "r"(v.y), "r"(v.z), "r"(v.w) : "memory");
}

__global__ void k_scatter2(const int* __restrict__ ei, int E) {
    long long total = (long long)E * 5;
    long long half = total >> 1;
    long long idx = (long long)blockIdx.x * blockDim.x + threadIdx.x;
    if (idx >= half + (total & 1)) return;
    if (idx < half) { sc2_one(ei, E, idx); sc2_one(ei, E, idx + half + (total & 1)); }
    else sc2_one(ei, E, idx);
}

// --------------- final: out = log_softmax(dinv*agg2 + b2)  (half2 loads) -------
__global__ void k_final(const float* __restrict__ b2, float* __restrict__ out) {
    int gtid = blockIdx.x * blockDim.x + threadIdx.x;
    int row  = gtid >> 5;
    int lane = threadIdx.x & 31;
    if (row >= N_NODES) return;

    const __half2* rp2 = (const __half2*)&g_agg2[(long long)row * CDIM];
    unsigned hbits = 0;
    if (lane < 20) { __half2 h = __ldcg(&rp2[lane]); hbits = *(unsigned*)&h; }

    // col lane -> half2 #(lane>>1); col 32+lane (lane<8) -> half2 #(16 + (lane>>1))
    unsigned w0 = __shfl_sync(0xFFFFFFFFu, hbits, lane >> 1);
    unsigned w1 = __shfl_sync(0xFFFFFFFFu, hbits, 16 + (lane >> 1));
    __half2 h0 = *(__half2*)&w0, h1 = *(__half2*)&w1;
    float2 f0 = __half22float2(h0), f1 = __half22float2(h1);
    float v0 = (lane & 1) ? f0.y : f0.x;
    float v1 = (lane & 1) ? f1.y : f1.x;

    float s  = g_dinv[row];
    float a0 = s * v0 + __ldg(&b2[lane]);
    float a1 = (lane < 8) ? (s * v1 + __ldg(&b2[32 + lane])) : -3.4e38f;
    float m  = fmaxf(a0, a1);
    #pragma unroll
    for (int o = 16; o; o >>= 1) m = fmaxf(m, __shfl_xor_sync(0xFFFFFFFFu, m, o));
    float es = expf(a0 - m) + ((lane < 8) ? expf(a1 - m) : 0.f);
    #pragma unroll
    for (int o = 16; o; o >>= 1) es += __shfl_xor_sync(0xFFFFFFFFu, es, o);
    float l = m + logf(es);
    out[(long long)row * CDIM + lane] = a0 - l;
    if (lane < 8) out[(long long)row * CDIM + 32 + lane] = a1 - l;
}

// ---------------------------------------------------------------------------
extern "C" void kernel_launch(void* const* d_in, const int* in_sizes, int n_in,
                              void* d_out, int out_size) {
    const float* x  = (const float*)d_in[0];
    const int*   ei = (const int*)  d_in[1];
    const float* W1 = (const float*)d_in[2];
    const float* b1 = (const float*)d_in[3];
    const float* W2 = (const float*)d_in[4];
    const float* b2 = (const float*)d_in[5];
    float* out = (float*)d_out;
    const int E = in_sizes[1] / 2;

    static void* cnt_ptr = nullptr;
    if (cnt_ptr == nullptr) cudaGetSymbolAddress(&cnt_ptr, g_cnt);

    cudaMemsetAsync(cnt_ptr, 0, N_NODES * sizeof(int));

    const int* dstCol = ei + E;
    if (((uintptr_t)dstCol & 15) == 0) {
        int n4 = E >> 2, rem = E & 3;
        int blocks = (n4 + 255) / 256;
        if (blocks < 3) blocks = 3;          // blocks 0/1 convert W, block 2 does tail
        k_count_vec<<<blocks, 256>>>((const int4*)dstCol, n4, rem, W1, W2);
    } else {
        k_count<<<(E + 255) / 256, 256>>>(ei, E, W1, W2);
    }

    k_gemm1<<<(N_NODES + 127) / 128, 256>>>(x);
    {
        long long half = ((long long)E * 8) >> 1;
        k_scatter1<<<(int)((half + 255) / 256), 256>>>(ei, E);
    }
    k_gemm2<<<(N_NODES + 63) / 64, 256>>>(b1);
    {
        long long total = (long long)E * 5;
        long long work = (total >> 1) + (total & 1);
        k_scatter2<<<(int)((work + 255) / 256), 256>>>(ei, E);
    }
    k_final<<<(N_NODES * 32 + 255) / 256, 256>>>(b2, out);
}

// round 16
// speedup vs baseline: 1.0447x; 1.0447x over previous
#include <cuda_runtime.h>
#include <cuda_fp16.h>
#include <mma.h>
#include <stdint.h>
using namespace nvcuda;

#define N_NODES 100000
#define F_IN    128
#define HDIM    64
#define CDIM    40

// ---- scratch (device globals: no allocation allowed) ----
__device__ __align__(256) int    g_cnt [N_NODES];
__device__ __align__(256) float  g_dinv[N_NODES];
__device__ __align__(256) __half g_W1h [128 * 72];        // W1 f16, padded stride 72
__device__ __align__(256) __half g_W2h [64 * 56];         // W2 f16, padded stride 56
__device__ __align__(256) __half g_h1s [N_NODES * HDIM];  // (x@W1)*dinv[row], f16
__device__ __align__(256) __half g_agg1[N_NODES * HDIM];  // init=self, += h1s[src]
__device__ __align__(256) __half g_h2s [N_NODES * CDIM];
__device__ __align__(256) __half g_agg2[N_NODES * CDIM];

// ------------------ degree count + one-time W1/W2 f16 conversion ----------
__global__ void k_count(const int* __restrict__ ei, int E,
                        const float* __restrict__ W1,
                        const float* __restrict__ W2) {
    if (blockIdx.x == 0) {        // W1 -> f16 padded [128][72]
        for (int i = threadIdx.x; i < 128 * 72; i += blockDim.x) {
            int k = i / 72, n = i % 72;
            g_W1h[i] = __float2half_rn(n < 64 ? W1[k * 64 + n] : 0.f);
        }
    } else if (blockIdx.x == 1) { // W2 -> f16 padded [64][56]
        for (int i = threadIdx.x; i < 64 * 56; i += blockDim.x) {
            int k = i / 56, n = i % 56;
            g_W2h[i] = __float2half_rn(n < 40 ? W2[k * 40 + n] : 0.f);
        }
    }
    int e = blockIdx.x * blockDim.x + threadIdx.x;
    if (e >= E) return;
    int d = __ldcg(&ei[E + e]);
    if ((unsigned)d < (unsigned)N_NODES) atomicAdd(&g_cnt[d], 1);
}

// ---- GEMM1 (tensor cores, pipelined, pre-converted W1h) ----------------------
#define WN 72
#define XS 40
#define ES 72
#define G1_SMEM (128*WN*2 + 2*128*XS*2)
__global__ __launch_bounds__(256, 3) void k_gemm1(const float* __restrict__ x) {
    __shared__ __align__(32) unsigned char sraw[G1_SMEM];
    __half* Wh  = (__half*)sraw;
    __half* Xh0 = (__half*)(sraw + 128 * WN * 2);
    __half* Xh1 = (__half*)(sraw + 128 * WN * 2 + 128 * XS * 2);
    float*  Es  = (float*)sraw;

    const int tid = threadIdx.x;
    const int wid = tid >> 5;
    const int warp_m = wid >> 1;
    const int warp_n = wid & 1;
    const int rowBase = blockIdx.x * 128;

    const int srow  = tid >> 1;
    const int kkOff = (tid & 1) * 16;
    const int grow  = rowBase + srow;
    const bool rowOK = (grow < N_NODES);
    const float* xrow = &x[(long long)grow * F_IN + kkOff];

    {   // copy pre-converted W1h (18432B) into smem
        const uint4* src = (const uint4*)g_W1h;
        uint4* dst = (uint4*)Wh;
        #pragma unroll
        for (int i = tid; i < 128 * WN * 2 / 16; i += 256) dst[i] = src[i];
    }

    {   // stage chunk 0
        __half* s = &Xh0[srow * XS + kkOff];
        if (rowOK) {
            #pragma unroll
            for (int q = 0; q < 4; q++) {
                float4 v = *(const float4*)(xrow + q * 4);
                *(__half2*)(s + q * 4)     = __float22half2_rn(make_float2(v.x, v.y));
                *(__half2*)(s + q * 4 + 2) = __float22half2_rn(make_float2(v.z, v.w));
            }
        } else {
            #pragma unroll
            for (int q = 0; q < 8; q++) *(__half2*)(s + q * 2) = __float2half2_rn(0.f);
        }
    }

    wmma::fragment<wmma::accumulator, 16, 16, 16, float> c[2][2];
    #pragma unroll
    for (int i = 0; i < 2; i++)
        #pragma unroll
        for (int j = 0; j < 2; j++) wmma::fill_fragment(c[i][j], 0.f);

    __syncthreads();

    #pragma unroll
    for (int ch = 0; ch < 4; ch++) {
        float4 p0, p1, p2, p3;
        if (ch < 3 && rowOK) {
            const float* xp = xrow + (ch + 1) * 32;
            p0 = *(const float4*)(xp);
            p1 = *(const float4*)(xp + 4);
            p2 = *(const float4*)(xp + 8);
            p3 = *(const float4*)(xp + 12);
        }

        const __half* Xb = (ch & 1) ? Xh1 : Xh0;
        #pragma unroll
        for (int kk = 0; kk < 32; kk += 16) {
            wmma::fragment<wmma::matrix_a, 16, 16, 16, __half, wmma::row_major> a[2];
            wmma::fragment<wmma::matrix_b, 16, 16, 16, __half, wmma::row_major> b[2];
            #pragma unroll
            for (int i = 0; i < 2; i++)
                wmma::load_matrix_sync(a[i], &Xb[(warp_m * 32 + i * 16) * XS + kk], XS);
            #pragma unroll
            for (int j = 0; j < 2; j++)
                wmma::load_matrix_sync(b[j], &Wh[(ch * 32 + kk) * WN + warp_n * 32 + j * 16], WN);
            #pragma unroll
            for (int i = 0; i < 2; i++)
                #pragma unroll
                for (int j = 0; j < 2; j++)
                    wmma::mma_sync(c[i][j], a[i], b[j], c[i][j]);
        }

        if (ch < 3) {
            __half* s = ((ch & 1) ? Xh0 : Xh1) + srow * XS + kkOff;
            if (rowOK) {
                *(__half2*)(s)      = __float22half2_rn(make_float2(p0.x, p0.y));
                *(__half2*)(s + 2)  = __float22half2_rn(make_float2(p0.z, p0.w));
                *(__half2*)(s + 4)  = __float22half2_rn(make_float2(p1.x, p1.y));
                *(__half2*)(s + 6)  = __float22half2_rn(make_float2(p1.z, p1.w));
                *(__half2*)(s + 8)  = __float22half2_rn(make_float2(p2.x, p2.y));
                *(__half2*)(s + 10) = __float22half2_rn(make_float2(p2.z, p2.w));
                *(__half2*)(s + 12) = __float22half2_rn(make_float2(p3.x, p3.y));
                *(__half2*)(s + 14) = __float22half2_rn(make_float2(p3.z, p3.w));
            } else {
                #pragma unroll
                for (int q = 0; q < 8; q++) *(__half2*)(s + q * 2) = __float2half2_rn(0.f);
            }
        }
        __syncthreads();
    }

    #pragma unroll
    for (int i = 0; i < 2; i++)
        #pragma unroll
        for (int j = 0; j < 2; j++)
            wmma::store_matrix_sync(&Es[(warp_m * 32 + i * 16) * ES + warp_n * 32 + j * 16],
                                    c[i][j], ES, wmma::mem_row_major);
    __syncthreads();

    {   // epilogue: dinv inline, scale, pack f16, dual-store
        int cb = (tid & 1) * 32;
        if (rowOK) {
            float s = rsqrtf(1.0f + (float)g_cnt[grow]);
            if (cb == 0) g_dinv[grow] = s;
            const float* ep = &Es[srow * ES + cb];
            __half* d1 = &g_h1s [(long long)grow * HDIM + cb];
            __half* d2 = &g_agg1[(long long)grow * HDIM + cb];
            #pragma unroll
            for (int q = 0; q < 8; q++) {
                float4 v = *(const float4*)(ep + q * 4);
                __half2 h0 = __float22half2_rn(make_float2(v.x * s, v.y * s));
                __half2 h1 = __float22half2_rn(make_float2(v.z * s, v.w * s));
                uint2 pk = make_uint2(*(unsigned*)&h0, *(unsigned*)&h1);
                *(uint2*)(d1 + q * 4) = pk;
                *(uint2*)(d2 + q * 4) = pk;
            }
        }
    }
}

// -------- scatter1: agg1[dst] += h1s[src], 4 independent chains per thread ------
__device__ __forceinline__ void sc1_one(const int* __restrict__ ei, int E, long long idx) {
    int e = (int)(idx >> 3);
    int c = ((int)idx & 7) * 8;
    int s = __ldcg(&ei[e]), d = __ldcg(&ei[E + e]);
    if ((unsigned)s >= (unsigned)N_NODES || (unsigned)d >= (unsigned)N_NODES) return;
    uint4 v = __ldcg((const uint4*)&g_h1s[(long long)s * HDIM + c]);
    __half* p = &g_agg1[(long long)d * HDIM + c];
    asm volatile("red.global.add.noftz.v4.f16x2 [%0], {%1, %2, %3, %4};"
                 :: "l"(p), "r"(v.x), "r"(v.y), "r"(v.z), "r"(v.w) : "memory");
}

__global__ void k_scatter1(const int* __restrict__ ei, int E) {
    long long total = (long long)E * 8;
    long long q = total >> 2;                 // E*8 divisible by 4
    long long idx = (long long)blockIdx.x * blockDim.x + threadIdx.x;
    if (idx >= q) return;
    sc1_one(ei, E, idx);
    sc1_one(ei, E, idx + q);
    sc1_one(ei, E, idx + 2 * q);
    sc1_one(ei, E, idx + 3 * q);
}

// ---- GEMM2 (tensor cores, 64-row tiles, per-warp Es epilogue) ----------------
#define W2S 56
#define X2S 72
#define E2S 48    // per-warp Es row stride (floats)
#define G2_SMEM (64*W2S*2 + 64*X2S*2 + 4*16*E2S*4)   // 28672
__global__ __launch_bounds__(256, 6) void k_gemm2(const float* __restrict__ b1) {
    __shared__ __align__(32) unsigned char sraw[G2_SMEM];
    __half* Wh = (__half*)sraw;
    __half* Xh = (__half*)(sraw + 64 * W2S * 2);
    float*  Es = (float*)(sraw + 64 * W2S * 2 + 64 * X2S * 2);  // [4 warps][16][48]
    __shared__ float Bs[64];

    const int tid = threadIdx.x;
    const int wid = tid >> 5;
    const int lane = tid & 31;
    const int rowBase = blockIdx.x * 64;

    const int srow = tid >> 2;
    const int kb   = (tid & 3) * 16;
    const int grow = rowBase + srow;
    const bool rowOK = (grow < N_NODES);

    __half2 xa[8];
    float di = 0.f;
    if (rowOK) {
        di = g_dinv[grow];
        const __half2* ap = (const __half2*)&g_agg1[(long long)grow * HDIM + kb];
        #pragma unroll
        for (int q = 0; q < 8; q++) xa[q] = __ldcg(&ap[q]);
    }

    {   // copy pre-converted W2h (7168B) into smem
        const uint4* src = (const uint4*)g_W2h;
        uint4* dst = (uint4*)Wh;
        #pragma unroll
        for (int i = tid; i < 64 * W2S * 2 / 16; i += 256) dst[i] = src[i];
    }
    if (tid < 64) Bs[tid] = b1[tid];
    __syncthreads();

    {   // convert: relu(dinv*agg1 + b1) -> f16 smem
        __half* s = &Xh[srow * X2S + kb];
        if (rowOK) {
            #pragma unroll
            for (int q = 0; q < 8; q++) {
                float2 f = __half22float2(xa[q]);
                float2 v = make_float2(fmaxf(di * f.x + Bs[kb + q*2],     0.f),
                                       fmaxf(di * f.y + Bs[kb + q*2 + 1], 0.f));
                *(__half2*)(s + q * 2) = __float22half2_rn(v);
            }
        } else {
            #pragma unroll
            for (int q = 0; q < 8; q++) *(__half2*)(s + q * 2) = __float2half2_rn(0.f);
        }
    }
    __syncthreads();   // last block-wide sync: Xh ready

    if (wid < 4) {     // mma warps run to completion independently
        wmma::fragment<wmma::accumulator, 16, 16, 16, float> c[3];
        #pragma unroll
        for (int j = 0; j < 3; j++) wmma::fill_fragment(c[j], 0.f);

        #pragma unroll
        for (int k = 0; k < 64; k += 16) {
            wmma::fragment<wmma::matrix_a, 16, 16, 16, __half, wmma::row_major> a;
            wmma::load_matrix_sync(a, &Xh[(wid * 16) * X2S + k], X2S);
            #pragma unroll
            for (int j = 0; j < 3; j++) {
                wmma::fragment<wmma::matrix_b, 16, 16, 16, __half, wmma::row_major> b;
                wmma::load_matrix_sync(b, &Wh[k * W2S + j * 16], W2S);
                wmma::mma_sync(c[j], a, b, c[j]);
            }
        }

        float* EsW = Es + wid * 16 * E2S;
        #pragma unroll
        for (int j = 0; j < 3; j++)
            wmma::store_matrix_sync(&EsW[j * 16], c[j], E2S, wmma::mem_row_major);
        __syncwarp();

        {   // per-warp epilogue: 16 rows x 2 halves
            int r  = lane >> 1;
            int cb = (lane & 1) * 20;
            int row = rowBase + wid * 16 + r;
            if (row < N_NODES) {
                float s = g_dinv[row];
                const float* ep = &EsW[r * E2S + cb];
                __half* d1 = &g_h2s [(long long)row * CDIM + cb];
                __half* d2 = &g_agg2[(long long)row * CDIM + cb];
                #pragma unroll
                for (int q = 0; q < 5; q++) {
                    float4 v = *(const float4*)(ep + q * 4);
                    __half2 h0 = __float22half2_rn(make_float2(v.x * s, v.y * s));
                    __half2 h1 = __float22half2_rn(make_float2(v.z * s, v.w * s));
                    uint2 pk = make_uint2(*(unsigned*)&h0, *(unsigned*)&h1);
                    *(uint2*)(d1 + q * 4) = pk;
                    *(uint2*)(d2 + q * 4) = pk;
                }
            }
        }
    }
}

// -------- scatter2: agg2[dst] += h2s[src], 4 independent chains per thread ------
__device__ __forceinline__ void sc2_one(const int* __restrict__ ei, int E, long long idx) {
    int e = (int)(idx / 5);
    int c = (int)(idx % 5) * 8;
    int s = __ldcg(&ei[e]), d = __ldcg(&ei[E + e]);
    if ((unsigned)s >= (unsigned)N_NODES || (unsigned)d >= (unsigned)N_NODES) return;
    uint4 v = __ldcg((const uint4*)&g_h2s[(long long)s * CDIM + c]);
    __half* p = &g_agg2[(long long)d * CDIM + c];
    asm volatile("red.global.add.noftz.v4.f16x2 [%0], {%1, %2, %3, %4};"
                 :: "l"(p), "r"(v.x), "r"(v.y), "r"(v.z), "r"(v.w) : "memory");
}

__global__ void k_scatter2(const int* __restrict__ ei, int E) {
    long long total = (long long)E * 5;
    long long q = total >> 2;
    long long rem = total - 4 * q;
    long long idx = (long long)blockIdx.x * blockDim.x + threadIdx.x;
    if (idx >= q) return;
    sc2_one(ei, E, idx);
    sc2_one(ei, E, idx + q);
    sc2_one(ei, E, idx + 2 * q);
    sc2_one(ei, E, idx + 3 * q);
    if (idx < rem) sc2_one(ei, E, 4 * q + idx);
}

// -------------------------------------- final: out = log_softmax(dinv*agg2 + b2)
__global__ void k_final(const float* __restrict__ b2, float* __restrict__ out) {
    int gtid = blockIdx.x * blockDim.x + threadIdx.x;
    int row  = gtid >> 5;
    int lane = threadIdx.x & 31;
    if (row >= N_NODES) return;
    const __half* rp = &g_agg2[(long long)row * CDIM];
    float s  = g_dinv[row];
    float a0 = s * __half2float(rp[lane]) + b2[lane];
    float a1 = (lane < 8) ? (s * __half2float(rp[32 + lane]) + b2[32 + lane]) : -3.4e38f;
    float m  = fmaxf(a0, a1);
    #pragma unroll
    for (int o = 16; o; o >>= 1) m = fmaxf(m, __shfl_xor_sync(0xFFFFFFFFu, m, o));
    float es = expf(a0 - m) + ((lane < 8) ? expf(a1 - m) : 0.f);
    #pragma unroll
    for (int o = 16; o; o >>= 1) es += __shfl_xor_sync(0xFFFFFFFFu, es, o);
    float l = m + logf(es);
    out[(long long)row * CDIM + lane] = a0 - l;
    if (lane < 8) out[(long long)row * CDIM + 32 + lane] = a1 - l;
}

// ---------------------------------------------------------------------------
extern "C" void kernel_launch(void* const* d_in, const int* in_sizes, int n_in,
                              void* d_out, int out_size) {
    const float* x  = (const float*)d_in[0];
    const int*   ei = (const int*)  d_in[1];
    const float* W1 = (const float*)d_in[2];
    const float* b1 = (const float*)d_in[3];
    const float* W2 = (const float*)d_in[4];
    const float* b2 = (const float*)d_in[5];
    float* out = (float*)d_out;
    const int E = in_sizes[1] / 2;

    static void* cnt_ptr = nullptr;
    if (cnt_ptr == nullptr) cudaGetSymbolAddress(&cnt_ptr, g_cnt);

    cudaMemsetAsync(cnt_ptr, 0, N_NODES * sizeof(int));
    k_count<<<(E + 255) / 256, 256>>>(ei, E, W1, W2);

    k_gemm1<<<(N_NODES + 127) / 128, 256>>>(x);
    {
        long long q = ((long long)E * 8) >> 2;
        k_scatter1<<<(int)((q + 255) / 256), 256>>>(ei, E);
    }
    k_gemm2<<<(N_NODES + 63) / 64, 256>>>(b1);
    {
        long long q = ((long long)E * 5) >> 2;
        k_scatter2<<<(int)((q + 255) / 256), 256>>>(ei, E);
    }
    k_final<<<(N_NODES * 32 + 255) / 256, 256>>>(b2, out);
}